// round 15
// baseline (speedup 1.0000x reference)
#include <cuda_runtime.h>
#include <cuda_fp16.h>
#include <cstdint>
#include <cstddef>

#define BATCH   32
#define NVARS   16
#define SAMPLES 4096
#define EMB     128
#define SPAD    4128      // padded sample rows (max needed s = 4123)
#define NTOK    1016
#define NST     64        // K stages: w2 = w*2 + half, K=64 fp16 each

// Scratch (device globals: allocation-free rule)
__device__ __align__(1024) __half g_enc[(size_t)BATCH * SPAD * EMB];   // ~33.8 MB
__device__ __align__(1024) __half g_wt[2ull * 128 * 4096];             // Wt[pass][n][k], 2 MB

// ======================= helpers =======================
__device__ __forceinline__ uint32_t smem_u32(const void* p) {
    uint32_t a;
    asm("{ .reg .u64 t; cvta.to.shared.u64 t, %1; cvt.u32.u64 %0, t; }" : "=r"(a) : "l"(p));
    return a;
}
#define CP16(dst, src) \
    asm volatile("cp.async.cg.shared.global [%0], [%1], 16;" :: "r"(dst), "l"(src))
#define CP_COMMIT()  asm volatile("cp.async.commit_group;" ::: "memory")
#define CP_WAIT(n)   asm volatile("cp.async.wait_group %0;" :: "n"(n) : "memory")

#define LDSM4(r, addr) \
    asm volatile("ldmatrix.sync.aligned.m8n8.x4.shared.b16 {%0,%1,%2,%3}, [%4];" \
        : "=r"((r)[0]), "=r"((r)[1]), "=r"((r)[2]), "=r"((r)[3]) : "r"(addr))

#define MMA16816(d, a, b0, b1) \
    asm volatile("mma.sync.aligned.m16n8k16.row.col.f32.f16.f16.f32 " \
        "{%0,%1,%2,%3}, {%4,%5,%6,%7}, {%8,%9}, {%0,%1,%2,%3};" \
        : "+f"((d)[0]), "+f"((d)[1]), "+f"((d)[2]), "+f"((d)[3]) \
        : "r"((a)[0]), "r"((a)[1]), "r"((a)[2]), "r"((a)[3]), "r"(b0), "r"(b1))

// ======================= Kernel 1: fused prep_w + encode (128-sample chunks) =======================
// Blocks [0,64):     split+transpose W_patch -> g_wt (64 k-rows x 128 n each)
// Blocks [64,1120):  encode 128 samples: enc[b,s,d] = floor(sum_v x*Ws + bs)
//                    idx = bx-64: b = idx&31, chunk = idx>>5 (33 chunks x 128 samples)
#define PREP_BLOCKS 64
#define ENC_CHUNKS  33           // ceil(SPAD/128)
#define ENC_BLOCKS  (ENC_CHUNKS * BATCH)   // 1056

__global__ void __launch_bounds__(256, 4)
prep_encode_kernel(const float* __restrict__ x,
                   const float* __restrict__ Ws,
                   const float* __restrict__ bs,
                   const float* __restrict__ Wp) {
    __shared__ __half tp_h[128][65];
    __shared__ __half tp_l[128][65];
    __shared__ float  xs[NVARS][128];
    int tid = threadIdx.x;
    int bx = blockIdx.x;

    if (bx < PREP_BLOCKS) {
        // ---- W split + transpose: 64 k-rows x 128 n ----
        int k0 = bx * 64;
#pragma unroll 4
        for (int i = 0; i < 32; i++) {
            int idx = tid + i * 256;          // 8192 elems
            int kr = idx >> 7, n = idx & 127;
            float w = Wp[(size_t)(k0 + kr) * 128 + n];
            __half hi = __float2half_rn(w);
            tp_h[n][kr] = hi;
            tp_l[n][kr] = __float2half_rn(w - __half2float(hi));
        }
        __syncthreads();
#pragma unroll 4
        for (int i = 0; i < 32; i++) {
            int idx = tid + i * 256;
            int n = idx >> 6, kr = idx & 63;  // coalesced 64-wide writes
            g_wt[(size_t)n * 4096 + k0 + kr]          = tp_h[n][kr];
            g_wt[524288 + (size_t)n * 4096 + k0 + kr] = tp_l[n][kr];
        }
    } else {
        // ---- encode: 128 samples per block ----
        int idx = bx - PREP_BLOCKS;
        int b = idx & 31;
        int s0 = (idx >> 5) * 128;
        {   // load 16v x 128s of x, 8 consecutive per thread (coalesced per v-row)
            int v = tid >> 4, sl = (tid & 15) * 8;
            const float* xrow = x + ((size_t)b * NVARS + v) * SAMPLES;
#pragma unroll
            for (int i = 0; i < 8; i++) {
                int sg = s0 + sl + i;
                xs[v][sl + i] = (sg < SAMPLES) ? xrow[sg] : 0.f;
            }
        }
        __syncthreads();
        int d = tid & 127;
        int sh = (tid >> 7) * 64;
        float wv[NVARS];
#pragma unroll
        for (int v = 0; v < NVARS; v++) wv[v] = Ws[v * EMB + d];
        float bias = bs[d];
        __half* erow = g_enc + ((size_t)b * SPAD + s0 + sh) * EMB + d;
#pragma unroll 16
        for (int s = 0; s < 64; s++) {
            int sg = s0 + sh + s;
            float acc = bias;
#pragma unroll
            for (int v = 0; v < NVARS; v++) acc += xs[v][sh + s] * wv[v];
            float val = (sg < SAMPLES) ? floorf(acc) : 0.f;
            if (sg < SPAD) erow[(size_t)s * EMB] = __float2half_rn(val);
        }
    }
}

// ======================= Kernel 2: windowed GEMM (R8-proven, frozen) =======================
// CTA tile: M=128 (64 tokens of batch b + 64 tokens of batch b+16), N=128; 128 threads.
// Warp grid 2x2, warp tile 64m x 64n. Schedule:
//   fill(it+1) -> CP_WAIT(1) -> bar -> compute(it) -> bar
// Stage smem: A 16KB + Bhi 16KB + Blo 16KB = 48KB; double buffered; 2 CTAs/SM.
// Rows are 128B (8 x 16B chunks), XOR swizzle chunk' = c ^ (row&7).
#define SM_A  1024u
#define SM_BH 17408u
#define SM_BL 33792u
#define STAGE_STRIDE 49152u
#define SMEM_BYTES (1024 + 2 * 49152)

__global__ void __launch_bounds__(128, 2)
gemm_kernel(const float* __restrict__ bp, float* __restrict__ out) {
    extern __shared__ char smem[];
    uint32_t sb = smem_u32(smem);
    int tid = threadIdx.x, wid = tid >> 5, lid = tid & 31;
    int t0 = blockIdx.x * 64;       // 64-token tile
    int b  = blockIdx.y;            // pair (b, b+16)

    ((float*)(smem + 512))[tid] = bp[tid];

    float acc[4][8][4];
#pragma unroll
    for (int i = 0; i < 4; i++)
#pragma unroll
        for (int j = 0; j < 8; j++)
#pragma unroll
            for (int k = 0; k < 4; k++) acc[i][j][k] = 0.f;

    // ---- producer addressing (128 threads; prow in [0,16), pc in [0,8)) ----
    int prow = tid >> 3, pc = tid & 7;
    const __half* aLo = g_enc + ((size_t)b * SPAD + (size_t)t0 * 4) * 128
                        + (size_t)prow * 512 + pc * 8;
    const __half* aHi = aLo + (size_t)16 * SPAD * 128;   // batch b+16
    const __half* bPt = g_wt + (size_t)prow * 4096 + pc * 8;
    uint32_t pdst = (uint32_t)prow * 128 + (uint32_t)((pc ^ (prow & 7)) << 4);

    auto fill = [&](int w2, int buf) {
        uint32_t st = (uint32_t)buf * STAGE_STRIDE;
        size_t off = (size_t)w2 * 64;
#pragma unroll
        for (int r = 0; r < 4; r++)   // A rows 0..63 (batch b): +16 rows = +16 tokens
            CP16(sb + SM_A + st + pdst + r * 2048u, (const void*)(aLo + off + (size_t)r * 8192));
#pragma unroll
        for (int r = 0; r < 4; r++)   // A rows 64..127 (batch b+16)
            CP16(sb + SM_A + st + 8192u + pdst + r * 2048u, (const void*)(aHi + off + (size_t)r * 8192));
#pragma unroll
        for (int r = 0; r < 8; r++)   // B hi: 128 n rows
            CP16(sb + SM_BH + st + pdst + r * 2048u, (const void*)(bPt + off + (size_t)r * 65536));
#pragma unroll
        for (int r = 0; r < 8; r++)   // B lo
            CP16(sb + SM_BL + st + pdst + r * 2048u, (const void*)(bPt + 524288 + off + (size_t)r * 65536));
        CP_COMMIT();
    };

    // ---- consumer addressing (warp tile 64m x 64n; warp grid 2x2) ----
    int wr = wid & 1, wc = wid >> 1;
    uint32_t xorv = (uint32_t)(lid & 7);
    uint32_t aRowOff[4], bRowOff[4];
#pragma unroll
    for (int mi = 0; mi < 4; mi++)
        aRowOff[mi] = (uint32_t)(wr * 64 + mi * 16 + (lid & 15)) * 128;
#pragma unroll
    for (int p = 0; p < 4; p++)
        bRowOff[p] = (uint32_t)(wc * 64 + p * 16 + (lid & 7) + ((lid & 16) ? 8 : 0)) * 128;
    uint32_t cbA = (uint32_t)(lid >> 4);
    uint32_t cbB = (uint32_t)((lid >> 3) & 1);

    auto compute = [&](int buf) {
        uint32_t st = (uint32_t)buf * STAGE_STRIDE;
        uint32_t baseA = sb + SM_A + st, baseBH = sb + SM_BH + st, baseBL = sb + SM_BL + st;
#pragma unroll
        for (int kk = 0; kk < 4; kk++) {
            uint32_t aSw = ((2u * kk + cbA) ^ xorv) << 4;
            uint32_t bSw = ((2u * kk + cbB) ^ xorv) << 4;
            uint32_t afr[4][4];
#pragma unroll
            for (int mi = 0; mi < 4; mi++)
                LDSM4(afr[mi], baseA + aRowOff[mi] + aSw);
            uint32_t bfr[4][4];
#pragma unroll
            for (int p = 0; p < 4; p++)
                LDSM4(bfr[p], baseBH + bRowOff[p] + bSw);
#pragma unroll
            for (int mi = 0; mi < 4; mi++)
#pragma unroll
                for (int p = 0; p < 4; p++) {
                    MMA16816(acc[mi][2 * p],     afr[mi], bfr[p][0], bfr[p][1]);
                    MMA16816(acc[mi][2 * p + 1], afr[mi], bfr[p][2], bfr[p][3]);
                }
#pragma unroll
            for (int p = 0; p < 4; p++)
                LDSM4(bfr[p], baseBL + bRowOff[p] + bSw);
#pragma unroll
            for (int mi = 0; mi < 4; mi++)
#pragma unroll
                for (int p = 0; p < 4; p++) {
                    MMA16816(acc[mi][2 * p],     afr[mi], bfr[p][0], bfr[p][1]);
                    MMA16816(acc[mi][2 * p + 1], afr[mi], bfr[p][2], bfr[p][3]);
                }
        }
    };

    // ---- R8-proven double-buffered loop ----
    fill(0, 0);
    for (int it = 0; it < NST; it++) {
        int buf = it & 1;
        if (it + 1 < NST) {
            fill(it + 1, buf ^ 1);
            CP_WAIT(1);            // stage(it) complete
        } else {
            CP_WAIT(0);
        }
        __syncthreads();
        compute(buf);
        __syncthreads();           // guard buffer reuse
    }

    // ---- epilogue: D + b_patch, floor, fp32 stores ----
    const float* bsm = (const float*)(smem + 512);
    int bOut = b + (wr ? 16 : 0);
    int rloc = lid >> 2;                        // row within the 64-token tile
    int nb = wc * 64 + (lid & 3) * 2;
#pragma unroll
    for (int mi = 0; mi < 4; mi++) {
        int trow0 = t0 + rloc + mi * 16;
#pragma unroll
        for (int ni = 0; ni < 8; ni++) {
            int n = nb + ni * 8;
            float bx = bsm[n], by = bsm[n + 1];
            if (trow0 < NTOK) {
                float2 v;
                v.x = floorf(acc[mi][ni][0] + bx);
                v.y = floorf(acc[mi][ni][1] + by);
                *(float2*)(out + ((size_t)bOut * NTOK + trow0) * 128 + n) = v;
            }
            if (trow0 + 8 < NTOK) {
                float2 v;
                v.x = floorf(acc[mi][ni][2] + bx);
                v.y = floorf(acc[mi][ni][3] + by);
                *(float2*)(out + ((size_t)bOut * NTOK + trow0 + 8) * 128 + n) = v;
            }
        }
    }
}

// ======================= launch =======================
extern "C" void kernel_launch(void* const* d_in, const int* in_sizes, int n_in,
                              void* d_out, int out_size) {
    const float* x  = (const float*)d_in[0];
    const float* Ws = (const float*)d_in[1];
    const float* bs = (const float*)d_in[2];
    const float* Wp = (const float*)d_in[3];
    const float* bp = (const float*)d_in[4];
    float* out = (float*)d_out;

    prep_encode_kernel<<<PREP_BLOCKS + ENC_BLOCKS, 256>>>(x, Ws, bs, Wp);

    cudaFuncSetAttribute(gemm_kernel, cudaFuncAttributeMaxDynamicSharedMemorySize, SMEM_BYTES);
    gemm_kernel<<<dim3(16, 16), 128, SMEM_BYTES>>>(bp, out);

    (void)in_sizes; (void)n_in; (void)out_size;
}

// round 16
// speedup vs baseline: 1.1885x; 1.1885x over previous
#include <cuda_runtime.h>
#include <cuda_fp16.h>
#include <cstdint>
#include <cstddef>

#define BATCH   32
#define NVARS   16
#define SAMPLES 4096
#define EMB     128
#define SPAD    4128      // padded sample rows (max needed s = 4123)
#define NTOK    1016
#define NST     64        // K stages: w2 = w*2 + half, K=64 fp16 each

// Scratch (device globals: allocation-free rule)
__device__ __align__(1024) __half g_enc[(size_t)BATCH * SPAD * EMB];   // ~33.8 MB
__device__ __align__(1024) __half g_wt[2ull * 128 * 4096];             // Wt[pass][n][k], 2 MB

// ======================= helpers =======================
__device__ __forceinline__ uint32_t smem_u32(const void* p) {
    uint32_t a;
    asm("{ .reg .u64 t; cvta.to.shared.u64 t, %1; cvt.u32.u64 %0, t; }" : "=r"(a) : "l"(p));
    return a;
}
#define CP16(dst, src) \
    asm volatile("cp.async.cg.shared.global [%0], [%1], 16;" :: "r"(dst), "l"(src))
#define CP_COMMIT()  asm volatile("cp.async.commit_group;" ::: "memory")
#define CP_WAIT(n)   asm volatile("cp.async.wait_group %0;" :: "n"(n) : "memory")

#define LDSM4(r, addr) \
    asm volatile("ldmatrix.sync.aligned.m8n8.x4.shared.b16 {%0,%1,%2,%3}, [%4];" \
        : "=r"((r)[0]), "=r"((r)[1]), "=r"((r)[2]), "=r"((r)[3]) : "r"(addr))

#define MMA16816(d, a, b0, b1) \
    asm volatile("mma.sync.aligned.m16n8k16.row.col.f32.f16.f16.f32 " \
        "{%0,%1,%2,%3}, {%4,%5,%6,%7}, {%8,%9}, {%0,%1,%2,%3};" \
        : "+f"((d)[0]), "+f"((d)[1]), "+f"((d)[2]), "+f"((d)[3]) \
        : "r"((a)[0]), "r"((a)[1]), "r"((a)[2]), "r"((a)[3]), "r"(b0), "r"(b1))

// ======================= Kernel 1: fused prep_w + encode (smem-free W-prep) =======================
// Blocks [0,256):   W split+transpose, register-only. Block bx: k-rows [bx*16, bx*16+16).
//                   Thread (half = tid>>7, n = tid&127): reads 8 coalesced k-rows at column n,
//                   writes one 16B vector per plane to g_wt[n][k0..k0+8].
// Blocks [256,...): encode (R8-verbatim, 16 samples/block): enc = floor(x·Ws + bs).
// Smem = 1KB (xs only) -> encode occupancy no longer capped by the W-prep arrays.
#define PREPW_BLOCKS 256
#define ENC_SBLK     258          // SPAD/16

__global__ void __launch_bounds__(256)
prep_encode_kernel(const float* __restrict__ x,
                   const float* __restrict__ Ws,
                   const float* __restrict__ bs,
                   const float* __restrict__ Wp) {
    __shared__ __align__(8) float xs[NVARS][16];
    int tid = threadIdx.x;
    int bx = blockIdx.x;

    if (bx < PREPW_BLOCKS) {
        // ---- W split + transpose, register-only ----
        int k0 = bx * 16 + (tid >> 7) * 8;   // 8-k subchunk per thread-half
        int n  = tid & 127;
        __align__(16) __half h8[8];
        __align__(16) __half l8[8];
#pragma unroll
        for (int kr = 0; kr < 8; kr++) {
            float w = Wp[(size_t)(k0 + kr) * 128 + n];   // coalesced across n
            __half hi = __float2half_rn(w);
            h8[kr] = hi;
            l8[kr] = __float2half_rn(w - __half2float(hi));
        }
        *(uint4*)(g_wt + (size_t)n * 4096 + k0)          = *(const uint4*)h8;
        *(uint4*)(g_wt + 524288 + (size_t)n * 4096 + k0) = *(const uint4*)l8;
    } else {
        // ---- encode: 16 samples (R8-verbatim) ----
        int idx = bx - PREPW_BLOCKS;
        int b = idx / ENC_SBLK;
        int s0 = (idx - b * ENC_SBLK) * 16;
        {
            int v = tid >> 4, s = tid & 15;
            int sg = s0 + s;
            xs[v][s] = (sg < SAMPLES) ? x[((size_t)b * NVARS + v) * SAMPLES + sg] : 0.f;
        }
        __syncthreads();
        int d = tid & 127;
        int sh = (tid >> 7) * 8;
        float wv[NVARS];
#pragma unroll
        for (int v = 0; v < NVARS; v++) wv[v] = Ws[v * EMB + d];
        float bias = bs[d];
#pragma unroll
        for (int s = 0; s < 8; s++) {
            int sg = s0 + sh + s;
            float acc = bias;
#pragma unroll
            for (int v = 0; v < NVARS; v++) acc += xs[v][sh + s] * wv[v];
            float val = (sg < SAMPLES) ? floorf(acc) : 0.f;
            g_enc[((size_t)b * SPAD + sg) * EMB + d] = __float2half_rn(val);
        }
    }
}

// ======================= Kernel 2: windowed GEMM (R8-proven, frozen) =======================
// CTA tile: M=128 (64 tokens of batch b + 64 tokens of batch b+16), N=128; 128 threads.
// Warp grid 2x2, warp tile 64m x 64n. Schedule:
//   fill(it+1) -> CP_WAIT(1) -> bar -> compute(it) -> bar
// Stage smem: A 16KB + Bhi 16KB + Blo 16KB = 48KB; double buffered; 2 CTAs/SM.
// Rows are 128B (8 x 16B chunks), XOR swizzle chunk' = c ^ (row&7).
#define SM_A  1024u
#define SM_BH 17408u
#define SM_BL 33792u
#define STAGE_STRIDE 49152u
#define SMEM_BYTES (1024 + 2 * 49152)

__global__ void __launch_bounds__(128, 2)
gemm_kernel(const float* __restrict__ bp, float* __restrict__ out) {
    extern __shared__ char smem[];
    uint32_t sb = smem_u32(smem);
    int tid = threadIdx.x, wid = tid >> 5, lid = tid & 31;
    int t0 = blockIdx.x * 64;       // 64-token tile
    int b  = blockIdx.y;            // pair (b, b+16)

    ((float*)(smem + 512))[tid] = bp[tid];

    float acc[4][8][4];
#pragma unroll
    for (int i = 0; i < 4; i++)
#pragma unroll
        for (int j = 0; j < 8; j++)
#pragma unroll
            for (int k = 0; k < 4; k++) acc[i][j][k] = 0.f;

    // ---- producer addressing (128 threads; prow in [0,16), pc in [0,8)) ----
    int prow = tid >> 3, pc = tid & 7;
    const __half* aLo = g_enc + ((size_t)b * SPAD + (size_t)t0 * 4) * 128
                        + (size_t)prow * 512 + pc * 8;
    const __half* aHi = aLo + (size_t)16 * SPAD * 128;   // batch b+16
    const __half* bPt = g_wt + (size_t)prow * 4096 + pc * 8;
    uint32_t pdst = (uint32_t)prow * 128 + (uint32_t)((pc ^ (prow & 7)) << 4);

    auto fill = [&](int w2, int buf) {
        uint32_t st = (uint32_t)buf * STAGE_STRIDE;
        size_t off = (size_t)w2 * 64;
#pragma unroll
        for (int r = 0; r < 4; r++)   // A rows 0..63 (batch b): +16 rows = +16 tokens
            CP16(sb + SM_A + st + pdst + r * 2048u, (const void*)(aLo + off + (size_t)r * 8192));
#pragma unroll
        for (int r = 0; r < 4; r++)   // A rows 64..127 (batch b+16)
            CP16(sb + SM_A + st + 8192u + pdst + r * 2048u, (const void*)(aHi + off + (size_t)r * 8192));
#pragma unroll
        for (int r = 0; r < 8; r++)   // B hi: 128 n rows
            CP16(sb + SM_BH + st + pdst + r * 2048u, (const void*)(bPt + off + (size_t)r * 65536));
#pragma unroll
        for (int r = 0; r < 8; r++)   // B lo
            CP16(sb + SM_BL + st + pdst + r * 2048u, (const void*)(bPt + 524288 + off + (size_t)r * 65536));
        CP_COMMIT();
    };

    // ---- consumer addressing (warp tile 64m x 64n; warp grid 2x2) ----
    int wr = wid & 1, wc = wid >> 1;
    uint32_t xorv = (uint32_t)(lid & 7);
    uint32_t aRowOff[4], bRowOff[4];
#pragma unroll
    for (int mi = 0; mi < 4; mi++)
        aRowOff[mi] = (uint32_t)(wr * 64 + mi * 16 + (lid & 15)) * 128;
#pragma unroll
    for (int p = 0; p < 4; p++)
        bRowOff[p] = (uint32_t)(wc * 64 + p * 16 + (lid & 7) + ((lid & 16) ? 8 : 0)) * 128;
    uint32_t cbA = (uint32_t)(lid >> 4);
    uint32_t cbB = (uint32_t)((lid >> 3) & 1);

    auto compute = [&](int buf) {
        uint32_t st = (uint32_t)buf * STAGE_STRIDE;
        uint32_t baseA = sb + SM_A + st, baseBH = sb + SM_BH + st, baseBL = sb + SM_BL + st;
#pragma unroll
        for (int kk = 0; kk < 4; kk++) {
            uint32_t aSw = ((2u * kk + cbA) ^ xorv) << 4;
            uint32_t bSw = ((2u * kk + cbB) ^ xorv) << 4;
            uint32_t afr[4][4];
#pragma unroll
            for (int mi = 0; mi < 4; mi++)
                LDSM4(afr[mi], baseA + aRowOff[mi] + aSw);
            uint32_t bfr[4][4];
#pragma unroll
            for (int p = 0; p < 4; p++)
                LDSM4(bfr[p], baseBH + bRowOff[p] + bSw);
#pragma unroll
            for (int mi = 0; mi < 4; mi++)
#pragma unroll
                for (int p = 0; p < 4; p++) {
                    MMA16816(acc[mi][2 * p],     afr[mi], bfr[p][0], bfr[p][1]);
                    MMA16816(acc[mi][2 * p + 1], afr[mi], bfr[p][2], bfr[p][3]);
                }
#pragma unroll
            for (int p = 0; p < 4; p++)
                LDSM4(bfr[p], baseBL + bRowOff[p] + bSw);
#pragma unroll
            for (int mi = 0; mi < 4; mi++)
#pragma unroll
                for (int p = 0; p < 4; p++) {
                    MMA16816(acc[mi][2 * p],     afr[mi], bfr[p][0], bfr[p][1]);
                    MMA16816(acc[mi][2 * p + 1], afr[mi], bfr[p][2], bfr[p][3]);
                }
        }
    };

    // ---- R8-proven double-buffered loop ----
    fill(0, 0);
    for (int it = 0; it < NST; it++) {
        int buf = it & 1;
        if (it + 1 < NST) {
            fill(it + 1, buf ^ 1);
            CP_WAIT(1);            // stage(it) complete
        } else {
            CP_WAIT(0);
        }
        __syncthreads();
        compute(buf);
        __syncthreads();           // guard buffer reuse
    }

    // ---- epilogue: D + b_patch, floor, fp32 stores ----
    const float* bsm = (const float*)(smem + 512);
    int bOut = b + (wr ? 16 : 0);
    int rloc = lid >> 2;                        // row within the 64-token tile
    int nb = wc * 64 + (lid & 3) * 2;
#pragma unroll
    for (int mi = 0; mi < 4; mi++) {
        int trow0 = t0 + rloc + mi * 16;
#pragma unroll
        for (int ni = 0; ni < 8; ni++) {
            int n = nb + ni * 8;
            float bx = bsm[n], by = bsm[n + 1];
            if (trow0 < NTOK) {
                float2 v;
                v.x = floorf(acc[mi][ni][0] + bx);
                v.y = floorf(acc[mi][ni][1] + by);
                *(float2*)(out + ((size_t)bOut * NTOK + trow0) * 128 + n) = v;
            }
            if (trow0 + 8 < NTOK) {
                float2 v;
                v.x = floorf(acc[mi][ni][2] + bx);
                v.y = floorf(acc[mi][ni][3] + by);
                *(float2*)(out + ((size_t)bOut * NTOK + trow0 + 8) * 128 + n) = v;
            }
        }
    }
}

// ======================= launch =======================
extern "C" void kernel_launch(void* const* d_in, const int* in_sizes, int n_in,
                              void* d_out, int out_size) {
    const float* x  = (const float*)d_in[0];
    const float* Ws = (const float*)d_in[1];
    const float* bs = (const float*)d_in[2];
    const float* Wp = (const float*)d_in[3];
    const float* bp = (const float*)d_in[4];
    float* out = (float*)d_out;

    prep_encode_kernel<<<PREPW_BLOCKS + ENC_SBLK * BATCH, 256>>>(x, Ws, bs, Wp);

    cudaFuncSetAttribute(gemm_kernel, cudaFuncAttributeMaxDynamicSharedMemorySize, SMEM_BYTES);
    gemm_kernel<<<dim3(16, 16), 128, SMEM_BYTES>>>(bp, out);

    (void)in_sizes; (void)n_in; (void)out_size;
}

// round 17
// speedup vs baseline: 1.2279x; 1.0331x over previous
#include <cuda_runtime.h>
#include <cuda_fp16.h>
#include <cstdint>
#include <cstddef>

#define BATCH   32
#define NVARS   16
#define SAMPLES 4096
#define EMB     128
#define SPAD    4128      // padded sample rows (max needed s = 4123)
#define NTOK    1016
#define NST     64        // K stages: w2 = w*2 + half, K=64 fp16 each

// Scratch (device globals: allocation-free rule)
__device__ __align__(1024) __half g_enc[(size_t)BATCH * SPAD * EMB];   // ~33.8 MB
__device__ __align__(1024) __half g_wt[2ull * 128 * 4096];             // Wt[pass][n][k], 2 MB

// ======================= helpers =======================
__device__ __forceinline__ uint32_t smem_u32(const void* p) {
    uint32_t a;
    asm("{ .reg .u64 t; cvta.to.shared.u64 t, %1; cvt.u32.u64 %0, t; }" : "=r"(a) : "l"(p));
    return a;
}
#define CP16(dst, src) \
    asm volatile("cp.async.cg.shared.global [%0], [%1], 16;" :: "r"(dst), "l"(src))
#define CP_COMMIT()  asm volatile("cp.async.commit_group;" ::: "memory")
#define CP_WAIT(n)   asm volatile("cp.async.wait_group %0;" :: "n"(n) : "memory")

#define LDSM4(r, addr) \
    asm volatile("ldmatrix.sync.aligned.m8n8.x4.shared.b16 {%0,%1,%2,%3}, [%4];" \
        : "=r"((r)[0]), "=r"((r)[1]), "=r"((r)[2]), "=r"((r)[3]) : "r"(addr))

#define MMA16816(d, a, b0, b1) \
    asm volatile("mma.sync.aligned.m16n8k16.row.col.f32.f16.f16.f32 " \
        "{%0,%1,%2,%3}, {%4,%5,%6,%7}, {%8,%9}, {%0,%1,%2,%3};" \
        : "+f"((d)[0]), "+f"((d)[1]), "+f"((d)[2]), "+f"((d)[3]) \
        : "r"((a)[0]), "r"((a)[1]), "r"((a)[2]), "r"((a)[3]), "r"(b0), "r"(b1))

// ======================= Kernel 1: fused prep_w + encode-as-MMA =======================
// Blocks [0,256):    W_patch split+transpose, register-only (R16-proven).
// Blocks [256,1312): encode via tensor cores. Per block: batch b, 128-sample chunk.
//   enc = floor(x^T·Ws + bs), computed as 3 fp16 MMA passes:
//   xh·Wh + xh·Wl + xl·Wh  (xl·Wl ~2^-22, dropped), fp32 accumulation.
//   fp16 tiles xh/xl [128s][16v], wh/wl [128d][16v]; rows padded to 48B so the
//   ldmatrix 8-row phases hit distinct banks (12r mod 32 all-distinct per 8 rows).
#define PREPW_BLOCKS 256
#define EMMA_CHUNKS  33                      // ceil(SPAD/128)
#define EMMA_BLOCKS  (EMMA_CHUNKS * BATCH)   // 1056

__global__ void __launch_bounds__(256)
prep_encode_kernel(const float* __restrict__ x,
                   const float* __restrict__ Ws,
                   const float* __restrict__ bs,
                   const float* __restrict__ Wp) {
    __shared__ float  xsm[NVARS][132];       // fp32 x chunk, padded
    __shared__ __half xh[128][24];           // [s][v], 48B rows
    __shared__ __half xl[128][24];
    __shared__ __half wh[128][24];           // [d][v], 48B rows
    __shared__ __half wl[128][24];
    __shared__ float  bsm[128];
    int tid = threadIdx.x;
    int bx = blockIdx.x;

    if (bx < PREPW_BLOCKS) {
        // ---- W split + transpose, register-only (R16-proven) ----
        int k0 = bx * 16 + (tid >> 7) * 8;
        int n  = tid & 127;
        __align__(16) __half h8[8];
        __align__(16) __half l8[8];
#pragma unroll
        for (int kr = 0; kr < 8; kr++) {
            float w = Wp[(size_t)(k0 + kr) * 128 + n];
            __half hi = __float2half_rn(w);
            h8[kr] = hi;
            l8[kr] = __float2half_rn(w - __half2float(hi));
        }
        *(uint4*)(g_wt + (size_t)n * 4096 + k0)          = *(const uint4*)h8;
        *(uint4*)(g_wt + 524288 + (size_t)n * 4096 + k0) = *(const uint4*)l8;
        return;
    }

    // ---- encode-as-MMA ----
    int id = bx - PREPW_BLOCKS;
    int b  = id & 31;
    int s0 = (id >> 5) * 128;

    // load x chunk [16v][128s] (coalesced per v-row), zero-padded
    {
        int v = tid >> 4, sb = (tid & 15) * 8;
        const float* xrow = x + ((size_t)b * NVARS + v) * SAMPLES;
#pragma unroll
        for (int i = 0; i < 8; i++) {
            int sg = s0 + sb + i;
            xsm[v][sb + i] = (sg < SAMPLES) ? xrow[sg] : 0.f;
        }
    }
    // Ws split + transpose into [d][v] tiles; bias
    if (tid < 128) bsm[tid] = bs[tid];
#pragma unroll
    for (int j = 0; j < 8; j++) {
        int e = tid + j * 256;               // e = v*128 + d
        int d = e & 127;
        int v = e >> 7;
        float w = Ws[e];
        __half h = __float2half_rn(w);
        wh[d][v] = h;
        wl[d][v] = __float2half_rn(w - __half2float(h));
    }
    __syncthreads();
    // x split into [s][v] tiles
#pragma unroll
    for (int j = 0; j < 8; j++) {
        int e = tid + j * 256;               // e = v*128 + s
        int s = e & 127;
        int v = e >> 7;
        float xv = xsm[v][s];
        __half h = __float2half_rn(xv);
        xh[s][v] = h;
        xl[s][v] = __float2half_rn(xv - __half2float(h));
    }
    __syncthreads();

    // warps: 2m x 4n grid; warp tile 64s x 32d
    int wid = tid >> 5, lid = tid & 31;
    int wm = (wid >> 2) * 64;
    int wn = (wid & 3) * 32;
    uint32_t xhB = smem_u32(xh), xlB = smem_u32(xl);
    uint32_t whB = smem_u32(wh), wlB = smem_u32(wl);

    float acc[4][4][4];                      // [msub][n8][4]
#pragma unroll
    for (int i = 0; i < 4; i++)
#pragma unroll
        for (int j = 0; j < 4; j++)
#pragma unroll
            for (int k = 0; k < 4; k++) acc[i][j][k] = 0.f;

    // B fragments: two n16 subtiles, hi and lo
    uint32_t bOff[2];
#pragma unroll
    for (int ns = 0; ns < 2; ns++)
        bOff[ns] = (uint32_t)(wn + ns * 16 + (lid & 7) + ((lid & 16) ? 8 : 0)) * 48
                   + ((lid >> 3) & 1) * 16;
    uint32_t bfrH[2][4], bfrL[2][4];
#pragma unroll
    for (int ns = 0; ns < 2; ns++) {
        LDSM4(bfrH[ns], whB + bOff[ns]);
        LDSM4(bfrL[ns], wlB + bOff[ns]);
    }

#pragma unroll
    for (int msub = 0; msub < 4; msub++) {
        uint32_t aOff = (uint32_t)(wm + msub * 16 + (lid & 15)) * 48 + (lid >> 4) * 16;
        uint32_t afrH[4], afrL[4];
        LDSM4(afrH, xhB + aOff);
        LDSM4(afrL, xlB + aOff);
#pragma unroll
        for (int ns = 0; ns < 2; ns++) {
            MMA16816(acc[msub][2 * ns],     afrH, bfrH[ns][0], bfrH[ns][1]);
            MMA16816(acc[msub][2 * ns + 1], afrH, bfrH[ns][2], bfrH[ns][3]);
            MMA16816(acc[msub][2 * ns],     afrH, bfrL[ns][0], bfrL[ns][1]);
            MMA16816(acc[msub][2 * ns + 1], afrH, bfrL[ns][2], bfrL[ns][3]);
            MMA16816(acc[msub][2 * ns],     afrL, bfrH[ns][0], bfrH[ns][1]);
            MMA16816(acc[msub][2 * ns + 1], afrL, bfrH[ns][2], bfrH[ns][3]);
        }
    }

    // epilogue: floor(acc + bias), fp16x2 stores (cols col, col+1)
#pragma unroll
    for (int msub = 0; msub < 4; msub++) {
        int row0 = wm + msub * 16 + (lid >> 2);
#pragma unroll
        for (int n8 = 0; n8 < 4; n8++) {
            int col = wn + n8 * 8 + (lid & 3) * 2;
            float bx0 = bsm[col], bx1 = bsm[col + 1];
            int sg0 = s0 + row0;
            if (sg0 < SPAD) {
                __half2 hv;
                hv.x = __float2half_rn(floorf(acc[msub][n8][0] + bx0));
                hv.y = __float2half_rn(floorf(acc[msub][n8][1] + bx1));
                *(__half2*)(g_enc + ((size_t)b * SPAD + sg0) * EMB + col) = hv;
            }
            int sg1 = sg0 + 8;
            if (sg1 < SPAD) {
                __half2 hv;
                hv.x = __float2half_rn(floorf(acc[msub][n8][2] + bx0));
                hv.y = __float2half_rn(floorf(acc[msub][n8][3] + bx1));
                *(__half2*)(g_enc + ((size_t)b * SPAD + sg1) * EMB + col) = hv;
            }
        }
    }
}

// ======================= Kernel 2: windowed GEMM (R8/R16-proven, frozen) =======================
// CTA tile: M=128 (64 tokens of batch b + 64 tokens of batch b+16), N=128; 128 threads.
// Warp grid 2x2, warp tile 64m x 64n. Schedule:
//   fill(it+1) -> CP_WAIT(1) -> bar -> compute(it) -> bar
// Stage smem: A 16KB + Bhi 16KB + Blo 16KB = 48KB; double buffered; 2 CTAs/SM.
// Rows are 128B (8 x 16B chunks), XOR swizzle chunk' = c ^ (row&7).
#define SM_A  1024u
#define SM_BH 17408u
#define SM_BL 33792u
#define STAGE_STRIDE 49152u
#define SMEM_BYTES (1024 + 2 * 49152)

__global__ void __launch_bounds__(128, 2)
gemm_kernel(const float* __restrict__ bp, float* __restrict__ out) {
    extern __shared__ char smem[];
    uint32_t sb = smem_u32(smem);
    int tid = threadIdx.x, wid = tid >> 5, lid = tid & 31;
    int t0 = blockIdx.x * 64;       // 64-token tile
    int b  = blockIdx.y;            // pair (b, b+16)

    ((float*)(smem + 512))[tid] = bp[tid];

    float acc[4][8][4];
#pragma unroll
    for (int i = 0; i < 4; i++)
#pragma unroll
        for (int j = 0; j < 8; j++)
#pragma unroll
            for (int k = 0; k < 4; k++) acc[i][j][k] = 0.f;

    // ---- producer addressing (128 threads; prow in [0,16), pc in [0,8)) ----
    int prow = tid >> 3, pc = tid & 7;
    const __half* aLo = g_enc + ((size_t)b * SPAD + (size_t)t0 * 4) * 128
                        + (size_t)prow * 512 + pc * 8;
    const __half* aHi = aLo + (size_t)16 * SPAD * 128;   // batch b+16
    const __half* bPt = g_wt + (size_t)prow * 4096 + pc * 8;
    uint32_t pdst = (uint32_t)prow * 128 + (uint32_t)((pc ^ (prow & 7)) << 4);

    auto fill = [&](int w2, int buf) {
        uint32_t st = (uint32_t)buf * STAGE_STRIDE;
        size_t off = (size_t)w2 * 64;
#pragma unroll
        for (int r = 0; r < 4; r++)   // A rows 0..63 (batch b): +16 rows = +16 tokens
            CP16(sb + SM_A + st + pdst + r * 2048u, (const void*)(aLo + off + (size_t)r * 8192));
#pragma unroll
        for (int r = 0; r < 4; r++)   // A rows 64..127 (batch b+16)
            CP16(sb + SM_A + st + 8192u + pdst + r * 2048u, (const void*)(aHi + off + (size_t)r * 8192));
#pragma unroll
        for (int r = 0; r < 8; r++)   // B hi: 128 n rows
            CP16(sb + SM_BH + st + pdst + r * 2048u, (const void*)(bPt + off + (size_t)r * 65536));
#pragma unroll
        for (int r = 0; r < 8; r++)   // B lo
            CP16(sb + SM_BL + st + pdst + r * 2048u, (const void*)(bPt + 524288 + off + (size_t)r * 65536));
        CP_COMMIT();
    };

    // ---- consumer addressing (warp tile 64m x 64n; warp grid 2x2) ----
    int wr = wid & 1, wc = wid >> 1;
    uint32_t xorv = (uint32_t)(lid & 7);
    uint32_t aRowOff[4], bRowOff[4];
#pragma unroll
    for (int mi = 0; mi < 4; mi++)
        aRowOff[mi] = (uint32_t)(wr * 64 + mi * 16 + (lid & 15)) * 128;
#pragma unroll
    for (int p = 0; p < 4; p++)
        bRowOff[p] = (uint32_t)(wc * 64 + p * 16 + (lid & 7) + ((lid & 16) ? 8 : 0)) * 128;
    uint32_t cbA = (uint32_t)(lid >> 4);
    uint32_t cbB = (uint32_t)((lid >> 3) & 1);

    auto compute = [&](int buf) {
        uint32_t st = (uint32_t)buf * STAGE_STRIDE;
        uint32_t baseA = sb + SM_A + st, baseBH = sb + SM_BH + st, baseBL = sb + SM_BL + st;
#pragma unroll
        for (int kk = 0; kk < 4; kk++) {
            uint32_t aSw = ((2u * kk + cbA) ^ xorv) << 4;
            uint32_t bSw = ((2u * kk + cbB) ^ xorv) << 4;
            uint32_t afr[4][4];
#pragma unroll
            for (int mi = 0; mi < 4; mi++)
                LDSM4(afr[mi], baseA + aRowOff[mi] + aSw);
            uint32_t bfr[4][4];
#pragma unroll
            for (int p = 0; p < 4; p++)
                LDSM4(bfr[p], baseBH + bRowOff[p] + bSw);
#pragma unroll
            for (int mi = 0; mi < 4; mi++)
#pragma unroll
                for (int p = 0; p < 4; p++) {
                    MMA16816(acc[mi][2 * p],     afr[mi], bfr[p][0], bfr[p][1]);
                    MMA16816(acc[mi][2 * p + 1], afr[mi], bfr[p][2], bfr[p][3]);
                }
#pragma unroll
            for (int p = 0; p < 4; p++)
                LDSM4(bfr[p], baseBL + bRowOff[p] + bSw);
#pragma unroll
            for (int mi = 0; mi < 4; mi++)
#pragma unroll
                for (int p = 0; p < 4; p++) {
                    MMA16816(acc[mi][2 * p],     afr[mi], bfr[p][0], bfr[p][1]);
                    MMA16816(acc[mi][2 * p + 1], afr[mi], bfr[p][2], bfr[p][3]);
                }
        }
    };

    // ---- R8-proven double-buffered loop ----
    fill(0, 0);
    for (int it = 0; it < NST; it++) {
        int buf = it & 1;
        if (it + 1 < NST) {
            fill(it + 1, buf ^ 1);
            CP_WAIT(1);            // stage(it) complete
        } else {
            CP_WAIT(0);
        }
        __syncthreads();
        compute(buf);
        __syncthreads();           // guard buffer reuse
    }

    // ---- epilogue: D + b_patch, floor, fp32 stores ----
    const float* bsm = (const float*)(smem + 512);
    int bOut = b + (wr ? 16 : 0);
    int rloc = lid >> 2;                        // row within the 64-token tile
    int nb = wc * 64 + (lid & 3) * 2;
#pragma unroll
    for (int mi = 0; mi < 4; mi++) {
        int trow0 = t0 + rloc + mi * 16;
#pragma unroll
        for (int ni = 0; ni < 8; ni++) {
            int n = nb + ni * 8;
            float bx = bsm[n], by = bsm[n + 1];
            if (trow0 < NTOK) {
                float2 v;
                v.x = floorf(acc[mi][ni][0] + bx);
                v.y = floorf(acc[mi][ni][1] + by);
                *(float2*)(out + ((size_t)bOut * NTOK + trow0) * 128 + n) = v;
            }
            if (trow0 + 8 < NTOK) {
                float2 v;
                v.x = floorf(acc[mi][ni][2] + bx);
                v.y = floorf(acc[mi][ni][3] + by);
                *(float2*)(out + ((size_t)bOut * NTOK + trow0 + 8) * 128 + n) = v;
            }
        }
    }
}

// ======================= launch =======================
extern "C" void kernel_launch(void* const* d_in, const int* in_sizes, int n_in,
                              void* d_out, int out_size) {
    const float* x  = (const float*)d_in[0];
    const float* Ws = (const float*)d_in[1];
    const float* bs = (const float*)d_in[2];
    const float* Wp = (const float*)d_in[3];
    const float* bp = (const float*)d_in[4];
    float* out = (float*)d_out;

    prep_encode_kernel<<<PREPW_BLOCKS + EMMA_BLOCKS, 256>>>(x, Ws, bs, Wp);

    cudaFuncSetAttribute(gemm_kernel, cudaFuncAttributeMaxDynamicSharedMemorySize, SMEM_BYTES);
    gemm_kernel<<<dim3(16, 16), 128, SMEM_BYTES>>>(bp, out);

    (void)in_sizes; (void)n_in; (void)out_size;
}